// round 14
// baseline (speedup 1.0000x reference)
#include <cuda_runtime.h>
#include <math.h>

// Problem sizes (fixed by the dataset)
#define TT 512
#define BB 256
#define II 256
#define HH 256
#define NG2 64        // groups of 4 batch rows

// -------- scratch (device globals: allocation-free contract) --------
__device__ float g_xp[(size_t)3 * TT * BB * HH];     // projections [mat][t][b][h]
// k-blocked transposed U: g_u4[m][((k>>2)*HH + j)*4 + (k&3)] = U_m[j*HH + k]
__device__ float g_u4[3][HH * HH];
// partial buffers: pA[group][slice][khalf][8 vals: za0..3,aa0..3][256 j]
__device__ float g_pA[NG2 * 4 * 2 * 8 * 256];        // 4 MB
__device__ float g_pB[NG2 * 4 * 2 * 4 * 256];        // 2 MB, vals d0..3
__device__ float g_S [NG2 * 4 * 4];                  // partial softmax sums [g][slice][row]
__device__ unsigned int g_fl[NG2 * 4 * TT * 2];      // flag [g][slice][t][stage]

// ---------------- asm helpers ----------------
__device__ __forceinline__ void ffma2(unsigned long long& d, unsigned long long a,
                                      unsigned long long b) {
    asm("fma.rn.f32x2 %0, %1, %2, %0;" : "+l"(d) : "l"(a), "l"(b));
}
__device__ __forceinline__ unsigned long long fdup(float v) {
    unsigned long long r; unsigned int u = __float_as_uint(v);
    asm("mov.b64 %0, {%1, %1};" : "=l"(r) : "r"(u));
    return r;
}
__device__ __forceinline__ float ffold(unsigned long long v) {
    return __uint_as_float((unsigned int)(v & 0xffffffffull)) +
           __uint_as_float((unsigned int)(v >> 32));
}
__device__ __forceinline__ void st_release_u32(unsigned int* p, unsigned int v) {
    asm volatile("st.release.gpu.global.u32 [%0], %1;" :: "l"(p), "r"(v) : "memory");
}
__device__ __forceinline__ unsigned int ld_acquire_u32(const unsigned int* p) {
    unsigned int v;
    asm volatile("ld.acquire.gpu.global.u32 %0, [%1];" : "=r"(v) : "l"(p) : "memory");
    return v;
}
__device__ __forceinline__ float tanh_fast(float x) {
    float r; asm("tanh.approx.f32 %0, %1;" : "=f"(r) : "f"(x)); return r;
}
// wait on the 3 peer flags of (g, t, stage); every thread polls (its own
// acquire orders its subsequent partial reads; no extra barrier needed)
__device__ __forceinline__ void wait_peers(int g, int r, int t, int s) {
#pragma unroll
    for (int c = 0; c < 4; ++c) {
        if (c == r) continue;
        const unsigned int* f = &g_fl[((g * 4 + c) * TT + t) * 2 + s];
        while (ld_acquire_u32(f) == 0u) { }
    }
}

// ---------------------------------------------------------------
// Kernel 0: zero the flags (runs first on every graph replay)
// ---------------------------------------------------------------
__global__ void zero_flags() {
    int i = blockIdx.x * blockDim.x + threadIdx.x;
    if (i < NG2 * 4 * TT * 2) g_fl[i] = 0u;
}

// ---------------------------------------------------------------
// Kernel 1: re-block U into k-quad layout
// ---------------------------------------------------------------
__global__ void reblock_U(const float* __restrict__ Uz,
                          const float* __restrict__ Ua,
                          const float* __restrict__ Uh) {
    int idx = blockIdx.x * blockDim.x + threadIdx.x;
    if (idx >= HH * HH) return;
    int j = idx / HH;
    int k = idx % HH;
    int dst = ((k >> 2) * HH + j) * 4 + (k & 3);
    g_u4[0][dst] = Uz[idx];
    g_u4[1][dst] = Ua[idx];
    g_u4[2][dst] = Uh[idx];
}

// ---------------------------------------------------------------
// Kernel 2: projection GEMM with FFMA2 (unchanged, proven)
// ---------------------------------------------------------------
__global__ __launch_bounds__(256) void proj_gemm(
    const float* __restrict__ x,
    const float* __restrict__ Wz,
    const float* __restrict__ Wa,
    const float* __restrict__ Wh) {
    constexpr int BM = 128, BN = 128, BK = 16;
    __shared__ float As[BK][BM];
    __shared__ float Bs[BK][BN];

    const int m0 = blockIdx.x * BM;
    const int n0 = blockIdx.y * BN;
    const int mat = n0 >> 8;
    const int jb  = n0 & 255;
    const float* W = (mat == 0) ? Wz : ((mat == 1) ? Wa : Wh);

    const int tid = threadIdx.x;
    const int tx = tid & 15;
    const int ty = tid >> 4;
    const int lr = tid >> 2;
    const int lc = (tid & 3) * 4;

    unsigned long long acc2[8][4];
#pragma unroll
    for (int i = 0; i < 8; ++i)
#pragma unroll
        for (int p = 0; p < 4; ++p) acc2[i][p] = 0ull;

    for (int k0 = 0; k0 < II; k0 += BK) {
        float4 a0 = *(const float4*)(x + (size_t)(m0 + lr)      * II + k0 + lc);
        float4 a1 = *(const float4*)(x + (size_t)(m0 + lr + 64) * II + k0 + lc);
        float4 b0 = *(const float4*)(W + (size_t)(jb + lr)      * II + k0 + lc);
        float4 b1 = *(const float4*)(W + (size_t)(jb + lr + 64) * II + k0 + lc);

        __syncthreads();
        As[lc + 0][lr] = a0.x; As[lc + 1][lr] = a0.y; As[lc + 2][lr] = a0.z; As[lc + 3][lr] = a0.w;
        As[lc + 0][lr + 64] = a1.x; As[lc + 1][lr + 64] = a1.y; As[lc + 2][lr + 64] = a1.z; As[lc + 3][lr + 64] = a1.w;
        Bs[lc + 0][lr] = b0.x; Bs[lc + 1][lr] = b0.y; Bs[lc + 2][lr] = b0.z; Bs[lc + 3][lr] = b0.w;
        Bs[lc + 0][lr + 64] = b1.x; Bs[lc + 1][lr + 64] = b1.y; Bs[lc + 2][lr + 64] = b1.z; Bs[lc + 3][lr + 64] = b1.w;
        __syncthreads();

#pragma unroll
        for (int kk = 0; kk < BK; ++kk) {
            float4 ra0 = *(const float4*)&As[kk][ty * 8];
            float4 ra1 = *(const float4*)&As[kk][ty * 8 + 4];
            ulonglong2 rb0 = *(const ulonglong2*)&Bs[kk][tx * 8];
            ulonglong2 rb1 = *(const ulonglong2*)&Bs[kk][tx * 8 + 4];
            unsigned long long pa[8];
            pa[0] = fdup(ra0.x); pa[1] = fdup(ra0.y); pa[2] = fdup(ra0.z); pa[3] = fdup(ra0.w);
            pa[4] = fdup(ra1.x); pa[5] = fdup(ra1.y); pa[6] = fdup(ra1.z); pa[7] = fdup(ra1.w);
#pragma unroll
            for (int i = 0; i < 8; ++i) {
                ffma2(acc2[i][0], pa[i], rb0.x);
                ffma2(acc2[i][1], pa[i], rb0.y);
                ffma2(acc2[i][2], pa[i], rb1.x);
                ffma2(acc2[i][3], pa[i], rb1.y);
            }
        }
    }

#pragma unroll
    for (int i = 0; i < 8; ++i) {
        int row = m0 + ty * 8 + i;
        int b = row >> 9;             // T = 512
        int t = row & (TT - 1);
        float* o = g_xp + ((size_t)mat * TT + t) * (size_t)(BB * HH)
                        + (size_t)b * HH + jb + tx * 8;
        *(float4*)(o)     = *(const float4*)&acc2[i][0];
        *(float4*)(o + 4) = *(const float4*)&acc2[i][2];
    }
}

// ---------------- scan GEMV helpers (4-row groups) ----------------
// U2: smem U slice as 16B units (Uz at 0, Ua at +4096, Uh at +8192)
__device__ __forceinline__ void gemvA_slice(const ulonglong2* U2, const float* hsP,
                                            float* pAdst, int jq, int kqb) {
    unsigned long long za[4], aa[4];
#pragma unroll
    for (int q = 0; q < 4; ++q) { za[q] = 0ull; aa[q] = 0ull; }
#pragma unroll
    for (int q = 0; q < 8; ++q) {
        const int uq = (kqb + q) * 256 + jq;
        ulonglong2 uz = U2[uq];
        ulonglong2 ua = U2[4096 + uq];
        const float* hb = hsP + (kqb + q) * 4;
#pragma unroll
        for (int rr = 0; rr < 4; ++rr) {
            ulonglong2 hk = *(const ulonglong2*)(hb + rr * 64);
            ffma2(za[rr], hk.x, uz.x); ffma2(za[rr], hk.y, uz.y);
            ffma2(aa[rr], hk.x, ua.x); ffma2(aa[rr], hk.y, ua.y);
        }
    }
#pragma unroll
    for (int rr = 0; rr < 4; ++rr) {
        pAdst[rr * 256 + jq]       = ffold(za[rr]);
        pAdst[(4 + rr) * 256 + jq] = ffold(aa[rr]);
    }
}
__device__ __forceinline__ void gemvB_slice(const ulonglong2* U2, const float* ehP,
                                            float* pBdst, int jq, int kqb) {
    unsigned long long dd[4];
#pragma unroll
    for (int q = 0; q < 4; ++q) dd[q] = 0ull;
#pragma unroll
    for (int q = 0; q < 8; ++q) {
        ulonglong2 uh = U2[8192 + (kqb + q) * 256 + jq];
        const float* eb = ehP + (kqb + q) * 4;
#pragma unroll
        for (int rr = 0; rr < 4; ++rr) {
            ulonglong2 ek = *(const ulonglong2*)(eb + rr * 64);
            ffma2(dd[rr], ek.x, uh.x); ffma2(dd[rr], ek.y, uh.y);
        }
    }
#pragma unroll
    for (int rr = 0; rr < 4; ++rr) pBdst[rr * 256 + jq] = ffold(dd[rr]);
}

// ---------------------------------------------------------------
// Kernel 3: interleaved 2-group k-sliced scan.
// 128 CTAs = 32 group-pairs x 4 k-slices, 512 threads.
// CTA (gp, r): groups g0=2gp, g1=2gp+1 (4 batch rows each), k-slice r,
// U slice (192KB) in smem. Flag waits for one group hide behind the
// sibling group's GEMV compute.
// ---------------------------------------------------------------
__global__ __launch_bounds__(512, 1) void scan_kernel(
    const float* __restrict__ bz,
    const float* __restrict__ va,
    const float* __restrict__ bh,
    float* __restrict__ out) {
    extern __shared__ float sm[];
    float* sU   = sm;               // 49152 floats (192KB)
    float* hs0  = sm + 49152;       // h, group 0   [4 rows][64 k]
    float* hs1  = sm + 49408;       // h, group 1
    float* ehs0 = sm + 49664;       // e*h, group 0
    float* ehs1 = sm + 49920;       // e*h, group 1
    float* es   = sm + 50176;       // e scratch (reused per group)

    const int tid = threadIdx.x;
    const int gp = blockIdx.x >> 2;
    const int r  = blockIdx.x & 3;
    const int g0 = gp * 2, g1 = gp * 2 + 1;
    const int b00 = g0 * 4, b01 = g1 * 4;

    // ---- load U slice into smem ----
    {
        const float4* src = (const float4*)(&g_u4[0][0]);
        float4* dst = (float4*)sU;
        for (int i = tid; i < 12288; i += 512) {
            int m = i >> 12;
            int o = i & 4095;
            dst[i] = src[m * 16384 + r * 4096 + o];
        }
    }
    if (tid < 256) { hs0[tid] = 0.f; hs1[tid] = 0.f; }
    __syncthreads();

    // GEMV identity
    const int jq    = tid & 255;
    const int khalf = tid >> 8;
    const int kqb   = khalf * 8;
    // finalize identity (tid < 256): one (row, column) state element per group
    const int row = tid >> 6;             // 0..3
    const int jj  = tid & 63;
    const int jg  = r * 64 + jj;

    float bzv = 0.f, vav = 0.f, bhv = 0.f;
    if (tid < 256) { bzv = bz[jg]; vav = va[jg]; bhv = bh[jg]; }

    float h0 = 0.f, h1 = 0.f;             // states
    float z0 = 0.f, z1 = 0.f;             // gates carried A->B
    float xh1_hold = 0.f;                 // xh for g1 carried one iteration

    const float* __restrict__ XZ = g_xp;
    const float* __restrict__ XA = g_xp + (size_t)TT * BB * HH;
    const float* __restrict__ XH = g_xp + (size_t)2 * TT * BB * HH;

    const ulonglong2* U2 = (const ulonglong2*)sU;
    float* pA0 = g_pA + (size_t)((g0 * 4 + r) * 2 + khalf) * (8 * 256);
    float* pA1 = g_pA + (size_t)((g1 * 4 + r) * 2 + khalf) * (8 * 256);
    float* pB0 = g_pB + (size_t)((g0 * 4 + r) * 2 + khalf) * (4 * 256);
    float* pB1 = g_pB + (size_t)((g1 * 4 + r) * 2 + khalf) * (4 * 256);

    for (int t = 0; t < TT; ++t) {
        // per-step x prefetch (finalize threads only)
        float xz0 = 0.f, xa0 = 0.f, xh0 = 0.f, xz1 = 0.f, xa1 = 0.f, xh1_new = 0.f;
        if (tid < 256) {
            const size_t o0 = (size_t)t * (BB * HH) + (size_t)(b00 + row) * HH + jg;
            const size_t o1 = (size_t)t * (BB * HH) + (size_t)(b01 + row) * HH + jg;
            xz0 = XZ[o0]; xa0 = XA[o0]; xh0 = XH[o0];
            xz1 = XZ[o1]; xa1 = XA[o1]; xh1_new = XH[o1];
        }

        // ---- GA0: stage-A GEMV, group 0 ----
        gemvA_slice(U2, hs0, pA0, jq, kqb);
        __syncthreads();
        if (tid == 0) st_release_u32(&g_fl[((g0 * 4 + r) * TT + t) * 2 + 0], 1u);

        // ---- FB1(t-1): finalize B, group 1, previous step ----
        if (t > 0) {
            wait_peers(g1, r, t - 1, 1);
            if (tid < 256) {
                float ds = 0.f, S = 0.f;
#pragma unroll
                for (int c = 0; c < 4; ++c) {
                    const float* pb = g_pB + (size_t)((g1 * 4 + c) * 2) * (4 * 256)
                                    + row * 256 + jg;
                    ds += pb[0] + pb[4 * 256];
                    S  += g_S[(g1 * 4 + c) * 4 + row];
                }
                const float ht = tanhf(xh1_hold + ds / S + bhv);
                const float hn = h1 + z1 * (ht - h1);
                out[((size_t)(b01 + row) * TT + (t - 1)) * HH + jg] = hn;
                h1 = hn;
                hs1[tid] = hn;
            }
        }
        __syncthreads();

        // ---- GA1: stage-A GEMV, group 1 ----
        gemvA_slice(U2, hs1, pA1, jq, kqb);
        __syncthreads();
        if (tid == 0) st_release_u32(&g_fl[((g1 * 4 + r) * TT + t) * 2 + 0], 1u);

        // ---- FA0: finalize A, group 0 ----
        wait_peers(g0, r, t, 0);
        if (tid < 256) {
            float zs = 0.f, as = 0.f;
#pragma unroll
            for (int c = 0; c < 4; ++c) {
                const float* pa = g_pA + (size_t)((g0 * 4 + c) * 2) * (8 * 256) + jg;
                zs += pa[row * 256]           + pa[8 * 256 + row * 256];
                as += pa[(4 + row) * 256]     + pa[8 * 256 + (4 + row) * 256];
            }
            z0 = 1.f / (1.f + __expf(-(xz0 + zs + bzv)));
            const float e = __expf(tanh_fast(xa0 + as) * vav);
            es[tid]   = e;
            ehs0[tid] = e * h0;
        }
        __syncthreads();
        if (tid < 128) {        // partial softmax sums, group 0
            const int w = tid >> 5, lane = tid & 31;
            float se = es[w * 64 + lane] + es[w * 64 + 32 + lane];
#pragma unroll
            for (int o = 16; o > 0; o >>= 1) se += __shfl_xor_sync(0xffffffffu, se, o);
            if (lane == 0) g_S[(g0 * 4 + r) * 4 + w] = se;
        }

        // ---- GB0: stage-B GEMV, group 0 ----
        gemvB_slice(U2, ehs0, pB0, jq, kqb);
        __syncthreads();
        if (tid == 0) st_release_u32(&g_fl[((g0 * 4 + r) * TT + t) * 2 + 1], 1u);

        // ---- FA1: finalize A, group 1 ----
        wait_peers(g1, r, t, 0);
        if (tid < 256) {
            float zs = 0.f, as = 0.f;
#pragma unroll
            for (int c = 0; c < 4; ++c) {
                const float* pa = g_pA + (size_t)((g1 * 4 + c) * 2) * (8 * 256) + jg;
                zs += pa[row * 256]           + pa[8 * 256 + row * 256];
                as += pa[(4 + row) * 256]     + pa[8 * 256 + (4 + row) * 256];
            }
            z1 = 1.f / (1.f + __expf(-(xz1 + zs + bzv)));
            const float e = __expf(tanh_fast(xa1 + as) * vav);
            es[tid]   = e;
            ehs1[tid] = e * h1;
        }
        __syncthreads();
        if (tid < 128) {        // partial softmax sums, group 1
            const int w = tid >> 5, lane = tid & 31;
            float se = es[w * 64 + lane] + es[w * 64 + 32 + lane];
#pragma unroll
            for (int o = 16; o > 0; o >>= 1) se += __shfl_xor_sync(0xffffffffu, se, o);
            if (lane == 0) g_S[(g1 * 4 + r) * 4 + w] = se;
        }

        // ---- GB1: stage-B GEMV, group 1 ----
        gemvB_slice(U2, ehs1, pB1, jq, kqb);
        __syncthreads();
        if (tid == 0) st_release_u32(&g_fl[((g1 * 4 + r) * TT + t) * 2 + 1], 1u);

        // ---- FB0: finalize B, group 0, current step ----
        wait_peers(g0, r, t, 1);
        if (tid < 256) {
            float ds = 0.f, S = 0.f;
#pragma unroll
            for (int c = 0; c < 4; ++c) {
                const float* pb = g_pB + (size_t)((g0 * 4 + c) * 2) * (4 * 256)
                                + row * 256 + jg;
                ds += pb[0] + pb[4 * 256];
                S  += g_S[(g0 * 4 + c) * 4 + row];
            }
            const float ht = tanhf(xh0 + ds / S + bhv);
            const float hn = h0 + z0 * (ht - h0);
            out[((size_t)(b00 + row) * TT + t) * HH + jg] = hn;
            h0 = hn;
            hs0[tid] = hn;
        }
        xh1_hold = xh1_new;
        __syncthreads();
    }

    // ---- FB1 for the final step (t = TT-1) ----
    wait_peers(g1, r, TT - 1, 1);
    if (tid < 256) {
        float ds = 0.f, S = 0.f;
#pragma unroll
        for (int c = 0; c < 4; ++c) {
            const float* pb = g_pB + (size_t)((g1 * 4 + c) * 2) * (4 * 256)
                            + row * 256 + jg;
            ds += pb[0] + pb[4 * 256];
            S  += g_S[(g1 * 4 + c) * 4 + row];
        }
        const float ht = tanhf(xh1_hold + ds / S + bhv);
        const float hn = h1 + z1 * (ht - h1);
        out[((size_t)(b01 + row) * TT + (TT - 1)) * HH + jg] = hn;
        h1 = hn;
    }

    // h_last appended after outputs [B,T,H]
    if (tid < 256) {
        float* hl = out + (size_t)BB * TT * HH;
        hl[(size_t)(b00 + row) * HH + jg] = h0;
        hl[(size_t)(b01 + row) * HH + jg] = h1;
    }
}

// ---------------------------------------------------------------
// kernel_launch: zero flags -> reblock -> GEMM -> scan
// Inputs: x, W_z, U_z, b_z, W_a, U_a, v_a, W_h, U_h, b_h
// ---------------------------------------------------------------
extern "C" void kernel_launch(void* const* d_in, const int* in_sizes, int n_in,
                              void* d_out, int out_size) {
    const float* x  = (const float*)d_in[0];
    const float* Wz = (const float*)d_in[1];
    const float* Uz = (const float*)d_in[2];
    const float* bz = (const float*)d_in[3];
    const float* Wa = (const float*)d_in[4];
    const float* Ua = (const float*)d_in[5];
    const float* va = (const float*)d_in[6];
    const float* Wh = (const float*)d_in[7];
    const float* Uh = (const float*)d_in[8];
    const float* bh = (const float*)d_in[9];
    float* out = (float*)d_out;

    static bool attr_set = false;
    if (!attr_set) {
        cudaFuncSetAttribute(scan_kernel, cudaFuncAttributeMaxDynamicSharedMemorySize,
                             50432 * 4);
        attr_set = true;
    }

    zero_flags<<<(NG2 * 4 * TT * 2 + 255) / 256, 256>>>();
    reblock_U<<<(HH * HH + 255) / 256, 256>>>(Uz, Ua, Uh);

    dim3 grid_g((BB * TT) / 128, (3 * HH) / 128);
    proj_gemm<<<grid_g, 256>>>(x, Wz, Wa, Wh);

    scan_kernel<<<128, 512, 50432 * 4>>>(bz, va, bh, out);
}

// round 15
// speedup vs baseline: 1.0098x; 1.0098x over previous
#include <cuda_runtime.h>
#include <math.h>

// Problem sizes (fixed by the dataset)
#define TT 512
#define BB 256
#define II 256
#define HH 256
#define NG2 64        // groups of 4 batch rows

// -------- scratch (device globals: allocation-free contract) --------
__device__ float g_xp[(size_t)3 * TT * BB * HH];     // projections [mat][t][b][h]
// k-blocked transposed U: g_u4[m][((k>>2)*HH + j)*4 + (k&3)] = U_m[j*HH + k]
__device__ float g_u4[3][HH * HH];
// partial buffers: pA[group][slice][khalf][8 vals: za0..3,aa0..3][256 j]
__device__ float g_pA[NG2 * 4 * 2 * 8 * 256];        // 4 MB
__device__ float g_pB[NG2 * 4 * 2 * 4 * 256];        // 2 MB, vals d0..3
__device__ float g_S [NG2 * 4 * 4];                  // partial softmax sums [g][slice][row]
__device__ unsigned int g_fl[NG2 * 4 * TT * 2];      // flag [g][slice][t][stage]

// ---------------- asm helpers ----------------
__device__ __forceinline__ void ffma2(unsigned long long& d, unsigned long long a,
                                      unsigned long long b) {
    asm("fma.rn.f32x2 %0, %1, %2, %0;" : "+l"(d) : "l"(a), "l"(b));
}
__device__ __forceinline__ unsigned long long fdup(float v) {
    unsigned long long r; unsigned int u = __float_as_uint(v);
    asm("mov.b64 %0, {%1, %1};" : "=l"(r) : "r"(u));
    return r;
}
__device__ __forceinline__ float ffold(unsigned long long v) {
    return __uint_as_float((unsigned int)(v & 0xffffffffull)) +
           __uint_as_float((unsigned int)(v >> 32));
}
__device__ __forceinline__ void st_release_u32(unsigned int* p, unsigned int v) {
    asm volatile("st.release.gpu.global.u32 [%0], %1;" :: "l"(p), "r"(v) : "memory");
}
__device__ __forceinline__ unsigned int ld_acquire_u32(const unsigned int* p) {
    unsigned int v;
    asm volatile("ld.acquire.gpu.global.u32 %0, [%1];" : "=r"(v) : "l"(p) : "memory");
    return v;
}
__device__ __forceinline__ float tanh_fast(float x) {
    float r; asm("tanh.approx.f32 %0, %1;" : "=f"(r) : "f"(x)); return r;
}
// wait on the 3 peer flags of (g, t, stage); every thread polls (its own
// acquire orders its subsequent partial reads; no extra barrier needed)
__device__ __forceinline__ void wait_peers(int g, int r, int t, int s) {
#pragma unroll
    for (int c = 0; c < 4; ++c) {
        if (c == r) continue;
        const unsigned int* f = &g_fl[((g * 4 + c) * TT + t) * 2 + s];
        while (ld_acquire_u32(f) == 0u) { }
    }
}

// ---------------------------------------------------------------
// Kernel 0: zero the flags (runs first on every graph replay)
// ---------------------------------------------------------------
__global__ void zero_flags() {
    int i = blockIdx.x * blockDim.x + threadIdx.x;
    if (i < NG2 * 4 * TT * 2) g_fl[i] = 0u;
}

// ---------------------------------------------------------------
// Kernel 1: re-block U into k-quad layout
// ---------------------------------------------------------------
__global__ void reblock_U(const float* __restrict__ Uz,
                          const float* __restrict__ Ua,
                          const float* __restrict__ Uh) {
    int idx = blockIdx.x * blockDim.x + threadIdx.x;
    if (idx >= HH * HH) return;
    int j = idx / HH;
    int k = idx % HH;
    int dst = ((k >> 2) * HH + j) * 4 + (k & 3);
    g_u4[0][dst] = Uz[idx];
    g_u4[1][dst] = Ua[idx];
    g_u4[2][dst] = Uh[idx];
}

// ---------------------------------------------------------------
// Kernel 2: projection GEMM with FFMA2 (unchanged, proven)
// ---------------------------------------------------------------
__global__ __launch_bounds__(256) void proj_gemm(
    const float* __restrict__ x,
    const float* __restrict__ Wz,
    const float* __restrict__ Wa,
    const float* __restrict__ Wh) {
    constexpr int BM = 128, BN = 128, BK = 16;
    __shared__ float As[BK][BM];
    __shared__ float Bs[BK][BN];

    const int m0 = blockIdx.x * BM;
    const int n0 = blockIdx.y * BN;
    const int mat = n0 >> 8;
    const int jb  = n0 & 255;
    const float* W = (mat == 0) ? Wz : ((mat == 1) ? Wa : Wh);

    const int tid = threadIdx.x;
    const int tx = tid & 15;
    const int ty = tid >> 4;
    const int lr = tid >> 2;
    const int lc = (tid & 3) * 4;

    unsigned long long acc2[8][4];
#pragma unroll
    for (int i = 0; i < 8; ++i)
#pragma unroll
        for (int p = 0; p < 4; ++p) acc2[i][p] = 0ull;

    for (int k0 = 0; k0 < II; k0 += BK) {
        float4 a0 = *(const float4*)(x + (size_t)(m0 + lr)      * II + k0 + lc);
        float4 a1 = *(const float4*)(x + (size_t)(m0 + lr + 64) * II + k0 + lc);
        float4 b0 = *(const float4*)(W + (size_t)(jb + lr)      * II + k0 + lc);
        float4 b1 = *(const float4*)(W + (size_t)(jb + lr + 64) * II + k0 + lc);

        __syncthreads();
        As[lc + 0][lr] = a0.x; As[lc + 1][lr] = a0.y; As[lc + 2][lr] = a0.z; As[lc + 3][lr] = a0.w;
        As[lc + 0][lr + 64] = a1.x; As[lc + 1][lr + 64] = a1.y; As[lc + 2][lr + 64] = a1.z; As[lc + 3][lr + 64] = a1.w;
        Bs[lc + 0][lr] = b0.x; Bs[lc + 1][lr] = b0.y; Bs[lc + 2][lr] = b0.z; Bs[lc + 3][lr] = b0.w;
        Bs[lc + 0][lr + 64] = b1.x; Bs[lc + 1][lr + 64] = b1.y; Bs[lc + 2][lr + 64] = b1.z; Bs[lc + 3][lr + 64] = b1.w;
        __syncthreads();

#pragma unroll
        for (int kk = 0; kk < BK; ++kk) {
            float4 ra0 = *(const float4*)&As[kk][ty * 8];
            float4 ra1 = *(const float4*)&As[kk][ty * 8 + 4];
            ulonglong2 rb0 = *(const ulonglong2*)&Bs[kk][tx * 8];
            ulonglong2 rb1 = *(const ulonglong2*)&Bs[kk][tx * 8 + 4];
            unsigned long long pa[8];
            pa[0] = fdup(ra0.x); pa[1] = fdup(ra0.y); pa[2] = fdup(ra0.z); pa[3] = fdup(ra0.w);
            pa[4] = fdup(ra1.x); pa[5] = fdup(ra1.y); pa[6] = fdup(ra1.z); pa[7] = fdup(ra1.w);
#pragma unroll
            for (int i = 0; i < 8; ++i) {
                ffma2(acc2[i][0], pa[i], rb0.x);
                ffma2(acc2[i][1], pa[i], rb0.y);
                ffma2(acc2[i][2], pa[i], rb1.x);
                ffma2(acc2[i][3], pa[i], rb1.y);
            }
        }
    }

#pragma unroll
    for (int i = 0; i < 8; ++i) {
        int row = m0 + ty * 8 + i;
        int b = row >> 9;             // T = 512
        int t = row & (TT - 1);
        float* o = g_xp + ((size_t)mat * TT + t) * (size_t)(BB * HH)
                        + (size_t)b * HH + jb + tx * 8;
        *(float4*)(o)     = *(const float4*)&acc2[i][0];
        *(float4*)(o + 4) = *(const float4*)&acc2[i][2];
    }
}

// ---------------- scan GEMV helpers (4-row groups) ----------------
// U2: smem U slice as 16B units (Uz at 0, Ua at +4096, Uh at +8192)
__device__ __forceinline__ void gemvA_slice(const ulonglong2* U2, const float* hsP,
                                            float* pAdst, int jq, int kqb) {
    unsigned long long za[4], aa[4];
#pragma unroll
    for (int q = 0; q < 4; ++q) { za[q] = 0ull; aa[q] = 0ull; }
#pragma unroll
    for (int q = 0; q < 8; ++q) {
        const int uq = (kqb + q) * 256 + jq;
        ulonglong2 uz = U2[uq];
        ulonglong2 ua = U2[4096 + uq];
        const float* hb = hsP + (kqb + q) * 4;
#pragma unroll
        for (int rr = 0; rr < 4; ++rr) {
            ulonglong2 hk = *(const ulonglong2*)(hb + rr * 64);
            ffma2(za[rr], hk.x, uz.x); ffma2(za[rr], hk.y, uz.y);
            ffma2(aa[rr], hk.x, ua.x); ffma2(aa[rr], hk.y, ua.y);
        }
    }
#pragma unroll
    for (int rr = 0; rr < 4; ++rr) {
        pAdst[rr * 256 + jq]       = ffold(za[rr]);
        pAdst[(4 + rr) * 256 + jq] = ffold(aa[rr]);
    }
}
__device__ __forceinline__ void gemvB_slice(const ulonglong2* U2, const float* ehP,
                                            float* pBdst, int jq, int kqb) {
    unsigned long long dd[4];
#pragma unroll
    for (int q = 0; q < 4; ++q) dd[q] = 0ull;
#pragma unroll
    for (int q = 0; q < 8; ++q) {
        ulonglong2 uh = U2[8192 + (kqb + q) * 256 + jq];
        const float* eb = ehP + (kqb + q) * 4;
#pragma unroll
        for (int rr = 0; rr < 4; ++rr) {
            ulonglong2 ek = *(const ulonglong2*)(eb + rr * 64);
            ffma2(dd[rr], ek.x, uh.x); ffma2(dd[rr], ek.y, uh.y);
        }
    }
#pragma unroll
    for (int rr = 0; rr < 4; ++rr) pBdst[rr * 256 + jq] = ffold(dd[rr]);
}

// ---------------------------------------------------------------
// Kernel 3: interleaved 2-group k-sliced scan.
// 128 CTAs = 32 group-pairs x 4 k-slices, 512 threads.
// CTA (gp, r): groups g0=2gp, g1=2gp+1 (4 batch rows each), k-slice r,
// U slice (192KB) in smem. Flag waits for one group hide behind the
// sibling group's GEMV compute.
// ---------------------------------------------------------------
__global__ __launch_bounds__(512, 1) void scan_kernel(
    const float* __restrict__ bz,
    const float* __restrict__ va,
    const float* __restrict__ bh,
    float* __restrict__ out) {
    extern __shared__ float sm[];
    float* sU   = sm;               // 49152 floats (192KB)
    float* hs0  = sm + 49152;       // h, group 0   [4 rows][64 k]
    float* hs1  = sm + 49408;       // h, group 1
    float* ehs0 = sm + 49664;       // e*h, group 0
    float* ehs1 = sm + 49920;       // e*h, group 1
    float* es   = sm + 50176;       // e scratch (reused per group)

    const int tid = threadIdx.x;
    const int gp = blockIdx.x >> 2;
    const int r  = blockIdx.x & 3;
    const int g0 = gp * 2, g1 = gp * 2 + 1;
    const int b00 = g0 * 4, b01 = g1 * 4;

    // ---- load U slice into smem ----
    {
        const float4* src = (const float4*)(&g_u4[0][0]);
        float4* dst = (float4*)sU;
        for (int i = tid; i < 12288; i += 512) {
            int m = i >> 12;
            int o = i & 4095;
            dst[i] = src[m * 16384 + r * 4096 + o];
        }
    }
    if (tid < 256) { hs0[tid] = 0.f; hs1[tid] = 0.f; }
    __syncthreads();

    // GEMV identity
    const int jq    = tid & 255;
    const int khalf = tid >> 8;
    const int kqb   = khalf * 8;
    // finalize identity (tid < 256): one (row, column) state element per group
    const int row = tid >> 6;             // 0..3
    const int jj  = tid & 63;
    const int jg  = r * 64 + jj;

    float bzv = 0.f, vav = 0.f, bhv = 0.f;
    if (tid < 256) { bzv = bz[jg]; vav = va[jg]; bhv = bh[jg]; }

    float h0 = 0.f, h1 = 0.f;             // states
    float z0 = 0.f, z1 = 0.f;             // gates carried A->B
    float xh1_hold = 0.f;                 // xh for g1 carried one iteration

    const float* __restrict__ XZ = g_xp;
    const float* __restrict__ XA = g_xp + (size_t)TT * BB * HH;
    const float* __restrict__ XH = g_xp + (size_t)2 * TT * BB * HH;

    const ulonglong2* U2 = (const ulonglong2*)sU;
    float* pA0 = g_pA + (size_t)((g0 * 4 + r) * 2 + khalf) * (8 * 256);
    float* pA1 = g_pA + (size_t)((g1 * 4 + r) * 2 + khalf) * (8 * 256);
    float* pB0 = g_pB + (size_t)((g0 * 4 + r) * 2 + khalf) * (4 * 256);
    float* pB1 = g_pB + (size_t)((g1 * 4 + r) * 2 + khalf) * (4 * 256);

    for (int t = 0; t < TT; ++t) {
        // per-step x prefetch (finalize threads only)
        float xz0 = 0.f, xa0 = 0.f, xh0 = 0.f, xz1 = 0.f, xa1 = 0.f, xh1_new = 0.f;
        if (tid < 256) {
            const size_t o0 = (size_t)t * (BB * HH) + (size_t)(b00 + row) * HH + jg;
            const size_t o1 = (size_t)t * (BB * HH) + (size_t)(b01 + row) * HH + jg;
            xz0 = XZ[o0]; xa0 = XA[o0]; xh0 = XH[o0];
            xz1 = XZ[o1]; xa1 = XA[o1]; xh1_new = XH[o1];
        }

        // ---- GA0: stage-A GEMV, group 0 ----
        gemvA_slice(U2, hs0, pA0, jq, kqb);
        __syncthreads();
        if (tid == 0) st_release_u32(&g_fl[((g0 * 4 + r) * TT + t) * 2 + 0], 1u);

        // ---- FB1(t-1): finalize B, group 1, previous step ----
        if (t > 0) {
            wait_peers(g1, r, t - 1, 1);
            if (tid < 256) {
                float ds = 0.f, S = 0.f;
#pragma unroll
                for (int c = 0; c < 4; ++c) {
                    const float* pb = g_pB + (size_t)((g1 * 4 + c) * 2) * (4 * 256)
                                    + row * 256 + jg;
                    ds += pb[0] + pb[4 * 256];
                    S  += g_S[(g1 * 4 + c) * 4 + row];
                }
                const float ht = tanhf(xh1_hold + ds / S + bhv);
                const float hn = h1 + z1 * (ht - h1);
                out[((size_t)(b01 + row) * TT + (t - 1)) * HH + jg] = hn;
                h1 = hn;
                hs1[tid] = hn;
            }
        }
        __syncthreads();

        // ---- GA1: stage-A GEMV, group 1 ----
        gemvA_slice(U2, hs1, pA1, jq, kqb);
        __syncthreads();
        if (tid == 0) st_release_u32(&g_fl[((g1 * 4 + r) * TT + t) * 2 + 0], 1u);

        // ---- FA0: finalize A, group 0 ----
        wait_peers(g0, r, t, 0);
        if (tid < 256) {
            float zs = 0.f, as = 0.f;
#pragma unroll
            for (int c = 0; c < 4; ++c) {
                const float* pa = g_pA + (size_t)((g0 * 4 + c) * 2) * (8 * 256) + jg;
                zs += pa[row * 256]           + pa[8 * 256 + row * 256];
                as += pa[(4 + row) * 256]     + pa[8 * 256 + (4 + row) * 256];
            }
            z0 = 1.f / (1.f + __expf(-(xz0 + zs + bzv)));
            const float e = __expf(tanh_fast(xa0 + as) * vav);
            es[tid]   = e;
            ehs0[tid] = e * h0;
        }
        __syncthreads();
        if (tid < 128) {        // partial softmax sums, group 0
            const int w = tid >> 5, lane = tid & 31;
            float se = es[w * 64 + lane] + es[w * 64 + 32 + lane];
#pragma unroll
            for (int o = 16; o > 0; o >>= 1) se += __shfl_xor_sync(0xffffffffu, se, o);
            if (lane == 0) g_S[(g0 * 4 + r) * 4 + w] = se;
        }

        // ---- GB0: stage-B GEMV, group 0 ----
        gemvB_slice(U2, ehs0, pB0, jq, kqb);
        __syncthreads();
        if (tid == 0) st_release_u32(&g_fl[((g0 * 4 + r) * TT + t) * 2 + 1], 1u);

        // ---- FA1: finalize A, group 1 ----
        wait_peers(g1, r, t, 0);
        if (tid < 256) {
            float zs = 0.f, as = 0.f;
#pragma unroll
            for (int c = 0; c < 4; ++c) {
                const float* pa = g_pA + (size_t)((g1 * 4 + c) * 2) * (8 * 256) + jg;
                zs += pa[row * 256]           + pa[8 * 256 + row * 256];
                as += pa[(4 + row) * 256]     + pa[8 * 256 + (4 + row) * 256];
            }
            z1 = 1.f / (1.f + __expf(-(xz1 + zs + bzv)));
            const float e = __expf(tanh_fast(xa1 + as) * vav);
            es[tid]   = e;
            ehs1[tid] = e * h1;
        }
        __syncthreads();
        if (tid < 128) {        // partial softmax sums, group 1
            const int w = tid >> 5, lane = tid & 31;
            float se = es[w * 64 + lane] + es[w * 64 + 32 + lane];
#pragma unroll
            for (int o = 16; o > 0; o >>= 1) se += __shfl_xor_sync(0xffffffffu, se, o);
            if (lane == 0) g_S[(g1 * 4 + r) * 4 + w] = se;
        }

        // ---- GB1: stage-B GEMV, group 1 ----
        gemvB_slice(U2, ehs1, pB1, jq, kqb);
        __syncthreads();
        if (tid == 0) st_release_u32(&g_fl[((g1 * 4 + r) * TT + t) * 2 + 1], 1u);

        // ---- FB0: finalize B, group 0, current step ----
        wait_peers(g0, r, t, 1);
        if (tid < 256) {
            float ds = 0.f, S = 0.f;
#pragma unroll
            for (int c = 0; c < 4; ++c) {
                const float* pb = g_pB + (size_t)((g0 * 4 + c) * 2) * (4 * 256)
                                + row * 256 + jg;
                ds += pb[0] + pb[4 * 256];
                S  += g_S[(g0 * 4 + c) * 4 + row];
            }
            const float ht = tanhf(xh0 + ds / S + bhv);
            const float hn = h0 + z0 * (ht - h0);
            out[((size_t)(b00 + row) * TT + t) * HH + jg] = hn;
            h0 = hn;
            hs0[tid] = hn;
        }
        xh1_hold = xh1_new;
        __syncthreads();
    }

    // ---- FB1 for the final step (t = TT-1) ----
    wait_peers(g1, r, TT - 1, 1);
    if (tid < 256) {
        float ds = 0.f, S = 0.f;
#pragma unroll
        for (int c = 0; c < 4; ++c) {
            const float* pb = g_pB + (size_t)((g1 * 4 + c) * 2) * (4 * 256)
                            + row * 256 + jg;
            ds += pb[0] + pb[4 * 256];
            S  += g_S[(g1 * 4 + c) * 4 + row];
        }
        const float ht = tanhf(xh1_hold + ds / S + bhv);
        const float hn = h1 + z1 * (ht - h1);
        out[((size_t)(b01 + row) * TT + (TT - 1)) * HH + jg] = hn;
        h1 = hn;
    }

    // h_last appended after outputs [B,T,H]
    if (tid < 256) {
        float* hl = out + (size_t)BB * TT * HH;
        hl[(size_t)(b00 + row) * HH + jg] = h0;
        hl[(size_t)(b01 + row) * HH + jg] = h1;
    }
}

// ---------------------------------------------------------------
// kernel_launch: zero flags -> reblock -> GEMM -> scan
// Inputs: x, W_z, U_z, b_z, W_a, U_a, v_a, W_h, U_h, b_h
// ---------------------------------------------------------------
extern "C" void kernel_launch(void* const* d_in, const int* in_sizes, int n_in,
                              void* d_out, int out_size) {
    const float* x  = (const float*)d_in[0];
    const float* Wz = (const float*)d_in[1];
    const float* Uz = (const float*)d_in[2];
    const float* bz = (const float*)d_in[3];
    const float* Wa = (const float*)d_in[4];
    const float* Ua = (const float*)d_in[5];
    const float* va = (const float*)d_in[6];
    const float* Wh = (const float*)d_in[7];
    const float* Uh = (const float*)d_in[8];
    const float* bh = (const float*)d_in[9];
    float* out = (float*)d_out;

    static bool attr_set = false;
    if (!attr_set) {
        cudaFuncSetAttribute(scan_kernel, cudaFuncAttributeMaxDynamicSharedMemorySize,
                             50432 * 4);
        attr_set = true;
    }

    zero_flags<<<(NG2 * 4 * TT * 2 + 255) / 256, 256>>>();
    reblock_U<<<(HH * HH + 255) / 256, 256>>>(Uz, Ua, Uh);

    dim3 grid_g((BB * TT) / 128, (3 * HH) / 128);
    proj_gemm<<<grid_g, 256>>>(x, Wz, Wa, Wh);

    scan_kernel<<<128, 512, 50432 * 4>>>(bz, va, bh, out);
}